// round 3
// baseline (speedup 1.0000x reference)
#include <cuda_runtime.h>
#include <cstdint>

#define B_   32
#define L_   1024
#define EMB_ 512
#define OUT_ 64
#define H_   8

// Scratch (device globals: allocation-free per harness rules)
__device__ float g_q[B_*H_*L_*OUT_];   // [b,h,l,o]
__device__ float g_k[B_*H_*L_*OUT_];
__device__ float g_v[B_*H_*L_*OUT_];
__device__ float g_c[B_*L_*H_*OUT_];   // concat [b,l,h*o]

// ---------------------------------------------------------------------------
// Kernel 1: fused QKV projection.  C[m, n] over n in [0,1536): mat/head/col.
// Block tile 128(M) x 64(N), K-chunks of 16. Each thread: 8x4 outputs.
// ---------------------------------------------------------------------------
__global__ __launch_bounds__(256) void qkv_kernel(
    const float* __restrict__ joint,
    const float* __restrict__ Wq, const float* __restrict__ Wk, const float* __restrict__ Wv,
    const float* __restrict__ bq, const float* __restrict__ bk, const float* __restrict__ bv)
{
    const int mb  = blockIdx.x;         // 256 tiles of 128 rows
    const int nb  = blockIdx.y;         // 24 = 3 mats * 8 heads
    const int mat = nb >> 3, h = nb & 7;

    const float* W; const float* bias; float* out;
    if (mat == 0)      { W = Wq; bias = bq; out = g_q; }
    else if (mat == 1) { W = Wk; bias = bk; out = g_k; }
    else               { W = Wv; bias = bv; out = g_v; }
    W    += h * (EMB_ * OUT_);
    bias += h * OUT_;

    __shared__ float As[128][17];   // [m][k], pad -> broadcast-friendly reads
    __shared__ float Bs[16][64];    // [k][n]

    const int tid = threadIdx.x;
    const int tx  = tid & 15, ty = tid >> 4;

    float acc[8][4];
    #pragma unroll
    for (int i = 0; i < 8; i++)
        #pragma unroll
        for (int j = 0; j < 4; j++) acc[i][j] = 0.f;

    const float* Abase = joint + (size_t)mb * 128 * EMB_;

    for (int kb = 0; kb < EMB_; kb += 16) {
        #pragma unroll
        for (int f = tid; f < 512; f += 256) {           // 128 rows x 4 float4
            int row = f >> 2, c4 = (f & 3) << 2;
            float4 v = *(const float4*)(Abase + row * EMB_ + kb + c4);
            As[row][c4+0] = v.x; As[row][c4+1] = v.y;
            As[row][c4+2] = v.z; As[row][c4+3] = v.w;
        }
        {
            int kk = tid >> 4, c4 = (tid & 15) << 2;     // 16 x 16 float4
            *(float4*)&Bs[kk][c4] = *(const float4*)(W + (kb + kk) * OUT_ + c4);
        }
        __syncthreads();

        #pragma unroll
        for (int kk = 0; kk < 16; kk++) {
            float a[8];
            #pragma unroll
            for (int i = 0; i < 8; i++) a[i] = As[ty*8 + i][kk];   // broadcast
            float4 b4 = *(float4*)&Bs[kk][tx*4];
            #pragma unroll
            for (int i = 0; i < 8; i++) {
                acc[i][0] += a[i] * b4.x;  acc[i][1] += a[i] * b4.y;
                acc[i][2] += a[i] * b4.z;  acc[i][3] += a[i] * b4.w;
            }
        }
        __syncthreads();
    }

    float4 bb = *(const float4*)(bias + tx*4);
    #pragma unroll
    for (int i = 0; i < 8; i++) {
        int m = mb*128 + ty*8 + i;
        int b = m >> 10, l = m & 1023;
        float4 r;
        r.x = acc[i][0] + bb.x;  r.y = acc[i][1] + bb.y;
        r.z = acc[i][2] + bb.z;  r.w = acc[i][3] + bb.w;
        *(float4*)(out + (size_t)((b*H_ + h)*L_ + l) * OUT_ + tx*4) = r;
    }
}

// ---------------------------------------------------------------------------
// Kernel 2: masked attention, flash-style online softmax.
// Faithful semantics: z = (q_valid && k_valid) ? s*scale : 0  (NOT -inf),
// softmax over all 1024 keys. Block = one (b,h) x 64 query rows.
// Threads 16x16, each owns 4x4 of S/P and 4x4 of O. Swizzled smem tiles.
// ---------------------------------------------------------------------------
__global__ __launch_bounds__(256) void attn_kernel(const int* __restrict__ traj)
{
    const int qb = blockIdx.x;          // 16 q-tiles of 64 rows
    const int bh = blockIdx.y;          // 256 = b*8 + h
    const int b  = bh >> 3, h = bh & 7;

    // traj_len dtype sniff: int64 buffers have zero high words at odd int32
    // indices (values < 1024). Only touches first 128 bytes -> safe for both.
    int is64 = 1;
    #pragma unroll
    for (int i = 1; i < 32; i += 2) is64 &= (traj[i] == 0);
    const int T = is64 ? traj[2*b] : traj[b];

    __shared__ float Qs[64][64], Ks[64][64], Vs[64][64];   // 48 KB, swizzled

    const float scale = 0.044194173824159216f;  // 1/sqrt(512)
    const int tid = threadIdx.x;
    const int tx  = tid & 15, ty = tid >> 4;

    const size_t base = (size_t)bh * L_ * OUT_;
    const float* Qg = g_q + base + (size_t)(qb*64) * OUT_;

    // Load Q tile (scaled), swizzle: float4 col e4 stored at e4 ^ ((row>>2)&7)
    #pragma unroll
    for (int f = tid; f < 1024; f += 256) {
        int row = f >> 4, e4 = f & 15;
        float4 v = *(const float4*)(Qg + row*64 + e4*4);
        v.x *= scale; v.y *= scale; v.z *= scale; v.w *= scale;
        *(float4*)&Qs[row][(e4 ^ ((row>>2)&7)) << 2] = v;
    }

    float m_r[4], l_r[4], Oa[4][4];
    #pragma unroll
    for (int i = 0; i < 4; i++) {
        m_r[i] = -1e30f; l_r[i] = 0.f;
        #pragma unroll
        for (int j = 0; j < 4; j++) Oa[i][j] = 0.f;
    }

    const bool qv0 = (qb*64 + ty*4 + 0) < T;
    const bool qv1 = (qb*64 + ty*4 + 1) < T;
    const bool qv2 = (qb*64 + ty*4 + 2) < T;
    const bool qv3 = (qb*64 + ty*4 + 3) < T;
    const bool qvi[4] = {qv0, qv1, qv2, qv3};

    for (int kb = 0; kb < L_; kb += 64) {
        const float* Kg = g_k + base + (size_t)kb * OUT_;
        const float* Vg = g_v + base + (size_t)kb * OUT_;
        #pragma unroll
        for (int f = tid; f < 1024; f += 256) {
            int row = f >> 4, e4 = f & 15;
            int sw = (e4 ^ ((row>>2)&7)) << 2;
            *(float4*)&Ks[row][sw] = *(const float4*)(Kg + row*64 + e4*4);
            *(float4*)&Vs[row][sw] = *(const float4*)(Vg + row*64 + e4*4);
        }
        __syncthreads();

        // S = Q * K^T  (rows ty*4+i, cols tx*4+j)
        float s[4][4];
        #pragma unroll
        for (int i = 0; i < 4; i++)
            #pragma unroll
            for (int j = 0; j < 4; j++) s[i][j] = 0.f;

        #pragma unroll
        for (int e4 = 0; e4 < 16; e4++) {
            float4 q4[4], k4[4];
            #pragma unroll
            for (int i = 0; i < 4; i++)
                q4[i] = *(float4*)&Qs[ty*4 + i][(e4 ^ (ty & 7)) << 2];
            #pragma unroll
            for (int j = 0; j < 4; j++)
                k4[j] = *(float4*)&Ks[tx*4 + j][(e4 ^ (tx & 7)) << 2];
            #pragma unroll
            for (int i = 0; i < 4; i++)
                #pragma unroll
                for (int j = 0; j < 4; j++)
                    s[i][j] += q4[i].x*k4[j].x + q4[i].y*k4[j].y
                             + q4[i].z*k4[j].z + q4[i].w*k4[j].w;
        }

        // Mask (multiplicative -> masked entries become literal 0 pre-softmax)
        float p[4][4];
        #pragma unroll
        for (int j = 0; j < 4; j++) {
            bool kvj = (kb + tx*4 + j) < T;
            #pragma unroll
            for (int i = 0; i < 4; i++)
                p[i][j] = (qvi[i] && kvj) ? s[i][j] : 0.f;
        }

        // Online softmax update (row reductions across 16 tx lanes)
        #pragma unroll
        for (int i = 0; i < 4; i++) {
            float tm = fmaxf(fmaxf(p[i][0], p[i][1]), fmaxf(p[i][2], p[i][3]));
            #pragma unroll
            for (int off = 8; off >= 1; off >>= 1)
                tm = fmaxf(tm, __shfl_xor_sync(0xffffffffu, tm, off));
            float nm = fmaxf(m_r[i], tm);
            float fcorr = __expf(m_r[i] - nm);
            m_r[i] = nm;
            float rs = 0.f;
            #pragma unroll
            for (int j = 0; j < 4; j++) {
                p[i][j] = __expf(p[i][j] - nm);
                rs += p[i][j];
            }
            #pragma unroll
            for (int off = 8; off >= 1; off >>= 1)
                rs += __shfl_xor_sync(0xffffffffu, rs, off);
            l_r[i] = l_r[i] * fcorr + rs;
            #pragma unroll
            for (int j = 0; j < 4; j++) Oa[i][j] *= fcorr;
        }

        __syncthreads();   // all S reads of Ks done -> reuse Ks as P buffer

        #pragma unroll
        for (int i = 0; i < 4; i++) {
            float4 pv = make_float4(p[i][0], p[i][1], p[i][2], p[i][3]);
            *(float4*)&Ks[ty*4 + i][(tx ^ (ty & 7)) << 2] = pv;
        }
        __syncthreads();

        // O += P * V
        #pragma unroll
        for (int c4 = 0; c4 < 16; c4++) {
            float4 p4[4], v4[4];
            #pragma unroll
            for (int i = 0; i < 4; i++)
                p4[i] = *(float4*)&Ks[ty*4 + i][(c4 ^ (ty & 7)) << 2];
            #pragma unroll
            for (int cc = 0; cc < 4; cc++)
                v4[cc] = *(float4*)&Vs[c4*4 + cc][(tx ^ (c4 & 7)) << 2];
            #pragma unroll
            for (int i = 0; i < 4; i++) {
                Oa[i][0] += p4[i].x*v4[0].x + p4[i].y*v4[1].x + p4[i].z*v4[2].x + p4[i].w*v4[3].x;
                Oa[i][1] += p4[i].x*v4[0].y + p4[i].y*v4[1].y + p4[i].z*v4[2].y + p4[i].w*v4[3].y;
                Oa[i][2] += p4[i].x*v4[0].z + p4[i].y*v4[1].z + p4[i].z*v4[2].z + p4[i].w*v4[3].z;
                Oa[i][3] += p4[i].x*v4[0].w + p4[i].y*v4[1].w + p4[i].z*v4[2].w + p4[i].w*v4[3].w;
            }
        }
        __syncthreads();   // PV reads of Vs done before next tile load
    }

    // Normalize and store in concat layout [b, l, h, o]
    #pragma unroll
    for (int i = 0; i < 4; i++) {
        float inv = 1.0f / l_r[i];
        int q = qb*64 + ty*4 + i;
        float4 r;
        r.x = Oa[i][0]*inv; r.y = Oa[i][1]*inv;
        r.z = Oa[i][2]*inv; r.w = Oa[i][3]*inv;
        *(float4*)(g_c + (size_t)(((b*L_ + q)*H_ + h)*OUT_) + tx*4) = r;
    }
}

// ---------------------------------------------------------------------------
// Kernel 3: output projection  concat[32768,512] @ Wo[512,64] -> d_out
// ---------------------------------------------------------------------------
__global__ __launch_bounds__(256) void out_kernel(
    const float* __restrict__ Wo, float* __restrict__ outp)
{
    const int mb = blockIdx.x;   // 256 tiles of 128 rows

    __shared__ float As[128][17];
    __shared__ float Bs[16][64];

    const int tid = threadIdx.x;
    const int tx  = tid & 15, ty = tid >> 4;

    float acc[8][4];
    #pragma unroll
    for (int i = 0; i < 8; i++)
        #pragma unroll
        for (int j = 0; j < 4; j++) acc[i][j] = 0.f;

    const float* Abase = g_c + (size_t)mb * 128 * (H_*OUT_);

    for (int kb = 0; kb < H_*OUT_; kb += 16) {
        #pragma unroll
        for (int f = tid; f < 512; f += 256) {
            int row = f >> 2, c4 = (f & 3) << 2;
            float4 v = *(const float4*)(Abase + row * (H_*OUT_) + kb + c4);
            As[row][c4+0] = v.x; As[row][c4+1] = v.y;
            As[row][c4+2] = v.z; As[row][c4+3] = v.w;
        }
        {
            int kk = tid >> 4, c4 = (tid & 15) << 2;
            *(float4*)&Bs[kk][c4] = *(const float4*)(Wo + (kb + kk) * OUT_ + c4);
        }
        __syncthreads();

        #pragma unroll
        for (int kk = 0; kk < 16; kk++) {
            float a[8];
            #pragma unroll
            for (int i = 0; i < 8; i++) a[i] = As[ty*8 + i][kk];
            float4 b4 = *(float4*)&Bs[kk][tx*4];
            #pragma unroll
            for (int i = 0; i < 8; i++) {
                acc[i][0] += a[i] * b4.x;  acc[i][1] += a[i] * b4.y;
                acc[i][2] += a[i] * b4.z;  acc[i][3] += a[i] * b4.w;
            }
        }
        __syncthreads();
    }

    #pragma unroll
    for (int i = 0; i < 8; i++) {
        int m = mb*128 + ty*8 + i;
        float4 r;
        r.x = acc[i][0]; r.y = acc[i][1]; r.z = acc[i][2]; r.w = acc[i][3];
        *(float4*)(outp + (size_t)m * OUT_ + tx*4) = r;
    }
}

// ---------------------------------------------------------------------------
extern "C" void kernel_launch(void* const* d_in, const int* in_sizes, int n_in,
                              void* d_out, int out_size)
{
    const float* joint = (const float*)d_in[0];
    // d_in[1] = delta [B,L,L,2] -- unused by the reference math (mask shape only)
    const int*   traj  = (const int*)d_in[2];   // int64-or-int32, sniffed on device
    const float* Wq    = (const float*)d_in[3];
    const float* Wk    = (const float*)d_in[4];
    const float* Wv    = (const float*)d_in[5];
    const float* bq    = (const float*)d_in[6];
    const float* bk    = (const float*)d_in[7];
    const float* bv    = (const float*)d_in[8];
    const float* Wo    = (const float*)d_in[9];
    float* out = (float*)d_out;

    dim3 g1(256, 24);
    qkv_kernel<<<g1, 256>>>(joint, Wq, Wk, Wv, bq, bk, bv);

    dim3 g2(16, 256);
    attn_kernel<<<g2, 256>>>(traj);

    out_kernel<<<256, 256>>>(Wo, out);
}

// round 5
// speedup vs baseline: 2.8128x; 2.8128x over previous
#include <cuda_runtime.h>
#include <cstdint>

#define B_   32
#define L_   1024
#define EMB_ 512
#define OUT_ 64
#define H_   8

// Scratch (device globals: allocation-free per harness rules)
__device__ float g_q[B_*H_*L_*OUT_];   // [b,h,l,o]
__device__ float g_k[B_*H_*L_*OUT_];   // [b,h,l,o]
__device__ float g_v[B_*H_*L_*OUT_];   // [b,h,l,o]
__device__ float g_c[B_*L_*H_*OUT_];   // concat [b,l,h*o]

// ===========================================================================
// tf32 warp-MMA helpers (mma.sync m16n8k8 — baseline PTX, works on sm_103)
// ===========================================================================
__device__ __forceinline__ uint32_t f2tf32(float x) {
    uint32_t r;
    asm("cvt.rna.tf32.f32 %0, %1;" : "=r"(r) : "f"(x));
    return r;
}

// D(16x8,f32) += A(16x8,tf32,row) * B(8x8,tf32,col)
__device__ __forceinline__ void mma8(float* d, const uint32_t* a, const uint32_t* b) {
    asm volatile(
        "mma.sync.aligned.m16n8k8.row.col.f32.tf32.tf32.f32 "
        "{%0,%1,%2,%3}, {%4,%5,%6,%7}, {%8,%9}, {%0,%1,%2,%3};"
        : "+f"(d[0]), "+f"(d[1]), "+f"(d[2]), "+f"(d[3])
        : "r"(a[0]), "r"(a[1]), "r"(a[2]), "r"(a[3]), "r"(b[0]), "r"(b[1]));
}
// Fragment maps (lane = threadIdx & 31, g = lane>>2, t = lane&3):
//   A: a0=(g, t)  a1=(g+8, t)  a2=(g, t+4)  a3=(g+8, t+4)        [row, k]
//   B: b0=(t, g)  b1=(t+4, g)                                     [k, col]
//   D: d0=(g, 2t) d1=(g, 2t+1) d2=(g+8, 2t) d3=(g+8, 2t+1)        [row, col]

// ---------------------------------------------------------------------------
// Kernel 1: fused QKV projection, tf32 MMA.
// C[128x64] block tile, K=512 in chunks of 32. 8 warps = 4(M) x 2(N),
// warp tile 32x32 = 2 m16-tiles x 4 n8-tiles.
// ---------------------------------------------------------------------------
__global__ __launch_bounds__(256) void qkv_tc(
    const float* __restrict__ joint,
    const float* __restrict__ Wq, const float* __restrict__ Wk, const float* __restrict__ Wv,
    const float* __restrict__ bq, const float* __restrict__ bk, const float* __restrict__ bv)
{
    const int mb  = blockIdx.x;         // 256 tiles of 128 rows
    const int nb  = blockIdx.y;         // 24 = 3 mats * 8 heads
    const int mat = nb >> 3, h = nb & 7;

    const float* W; const float* bias; float* outg;
    if (mat == 0)      { W = Wq; bias = bq; outg = g_q; }
    else if (mat == 1) { W = Wk; bias = bk; outg = g_k; }
    else               { W = Wv; bias = bv; outg = g_v; }
    W    += h * (EMB_ * OUT_);
    bias += h * OUT_;

    __shared__ uint32_t As[128][36];   // stride 36 ≡ 4 (mod 32): A-frag conflict-free
    __shared__ uint32_t Bs[32][72];    // stride 72 ≡ 8 (mod 32): B-frag conflict-free

    const int tid  = threadIdx.x;
    const int wid  = tid >> 5, lane = tid & 31;
    const int g    = lane >> 2, t = lane & 3;
    const int wm   = (wid & 3) * 32;
    const int wn   = (wid >> 2) * 32;

    float acc[2][4][4];
    #pragma unroll
    for (int i = 0; i < 2; i++)
        #pragma unroll
        for (int j = 0; j < 4; j++)
            #pragma unroll
            for (int r = 0; r < 4; r++) acc[i][j][r] = 0.f;

    const float* Abase = joint + (size_t)mb * 128 * EMB_;

    for (int kb = 0; kb < EMB_; kb += 32) {
        #pragma unroll
        for (int f = tid; f < 1024; f += 256) {          // A: 128 x 32
            int row = f >> 3, c4 = (f & 7) << 2;
            float4 v = *(const float4*)(Abase + row * EMB_ + kb + c4);
            As[row][c4+0] = f2tf32(v.x); As[row][c4+1] = f2tf32(v.y);
            As[row][c4+2] = f2tf32(v.z); As[row][c4+3] = f2tf32(v.w);
        }
        #pragma unroll
        for (int f = tid; f < 512; f += 256) {           // B: 32 x 64
            int row = f >> 4, c4 = (f & 15) << 2;
            float4 v = *(const float4*)(W + (kb + row) * OUT_ + c4);
            Bs[row][c4+0] = f2tf32(v.x); Bs[row][c4+1] = f2tf32(v.y);
            Bs[row][c4+2] = f2tf32(v.z); Bs[row][c4+3] = f2tf32(v.w);
        }
        __syncthreads();

        #pragma unroll
        for (int ks = 0; ks < 4; ks++) {
            const int k0 = ks * 8;
            uint32_t a[2][4], b[4][2];
            #pragma unroll
            for (int i = 0; i < 2; i++) {
                int r0 = wm + i*16 + g;
                a[i][0] = As[r0][k0 + t];     a[i][1] = As[r0+8][k0 + t];
                a[i][2] = As[r0][k0 + t + 4]; a[i][3] = As[r0+8][k0 + t + 4];
            }
            #pragma unroll
            for (int j = 0; j < 4; j++) {
                int c = wn + j*8 + g;
                b[j][0] = Bs[k0 + t][c];
                b[j][1] = Bs[k0 + t + 4][c];
            }
            #pragma unroll
            for (int i = 0; i < 2; i++)
                #pragma unroll
                for (int j = 0; j < 4; j++)
                    mma8(acc[i][j], a[i], b[j]);
        }
        __syncthreads();
    }

    // Epilogue: + bias, store [b,h,l,o]
    #pragma unroll
    for (int i = 0; i < 2; i++) {
        #pragma unroll
        for (int half = 0; half < 2; half++) {
            int m = mb*128 + wm + i*16 + g + half*8;
            int b = m >> 10, l = m & 1023;
            float* dst = outg + (size_t)((b*H_ + h)*L_ + l) * OUT_;
            #pragma unroll
            for (int j = 0; j < 4; j++) {
                int c = wn + j*8 + t*2;
                float2 r;
                r.x = acc[i][j][half*2+0] + __ldg(bias + c);
                r.y = acc[i][j][half*2+1] + __ldg(bias + c + 1);
                *(float2*)(dst + c) = r;
            }
        }
    }
}

// ---------------------------------------------------------------------------
// Kernel 2: attention, tf32 MMA. Block = one (b,h) x 128 q-rows, 8 warps.
// S = Q K^T in regs -> mask/exp in regs (no max subtraction; |z| <= ~1)
// -> P to smem (tf32) -> O += P V in regs, l as per-thread partials.
// ---------------------------------------------------------------------------
#define QS_OFF 0
#define KS_OFF 34816
#define VS_OFF 69632
#define PS_OFF 106496
#define LB_OFF 174080
#define SMEM_ATTN 176128

__global__ __launch_bounds__(256) void attn_tc(const int* __restrict__ traj)
{
    extern __shared__ char smem[];
    uint32_t (*Qs)[68]  = (uint32_t(*)[68])(smem + QS_OFF);   // 68 ≡ 4 : A-frag
    uint32_t (*Ks)[68]  = (uint32_t(*)[68])(smem + KS_OFF);   // S-mma B reads row-pattern
    uint32_t (*Vs)[72]  = (uint32_t(*)[72])(smem + VS_OFF);   // 72 ≡ 8 : B-frag
    uint32_t (*Ps)[132] = (uint32_t(*)[132])(smem + PS_OFF);  // 132 ≡ 4 : A-frag
    float    (*Lb)[4]   = (float(*)[4])(smem + LB_OFF);

    const int qb = blockIdx.x;          // 8 q-tiles of 128 rows
    const int bh = blockIdx.y;          // 256
    const int b  = bh >> 3, h = bh & 7;

    const int tid  = threadIdx.x;
    const int wid  = tid >> 5, lane = tid & 31;
    const int g    = lane >> 2, t = lane & 3;
    const int wm   = (wid & 1)  * 64;   // same M-half for S and O
    const int wnS  = (wid >> 1) * 32;   // S: 4 warp-cols of 32
    const int wnO  = (wid >> 1) * 16;   // O: 4 warp-cols of 16

    // traj_len dtype sniff (int64 -> odd int32 words zero; values < 1024)
    int is64 = 1;
    #pragma unroll
    for (int i = 1; i < 32; i += 2) is64 &= (traj[i] == 0);
    const int T = is64 ? traj[2*b] : traj[b];

    const float scale = 0.044194173824159216f;  // 1/sqrt(512)

    // Load Q tile [128,64], pre-scaled, tf32
    const float* Qg = g_q + (size_t)bh * L_ * OUT_ + (size_t)(qb*128) * OUT_;
    #pragma unroll
    for (int f = tid; f < 2048; f += 256) {
        int row = f >> 4, c4 = (f & 15) << 2;
        float4 v = *(const float4*)(Qg + row*64 + c4);
        Qs[row][c4+0] = f2tf32(v.x*scale); Qs[row][c4+1] = f2tf32(v.y*scale);
        Qs[row][c4+2] = f2tf32(v.z*scale); Qs[row][c4+3] = f2tf32(v.w*scale);
    }

    float oacc[4][2][4];
    #pragma unroll
    for (int i = 0; i < 4; i++)
        #pragma unroll
        for (int j = 0; j < 2; j++)
            #pragma unroll
            for (int r = 0; r < 4; r++) oacc[i][j][r] = 0.f;
    float lp[8];
    #pragma unroll
    for (int i = 0; i < 8; i++) lp[i] = 0.f;

    bool qv[8];
    #pragma unroll
    for (int i = 0; i < 4; i++) {
        qv[i*2+0] = (qb*128 + wm + i*16 + g)     < T;
        qv[i*2+1] = (qb*128 + wm + i*16 + g + 8) < T;
    }

    const float* Kg = g_k + (size_t)bh * L_ * OUT_;
    const float* Vg = g_v + (size_t)bh * L_ * OUT_;

    for (int kb = 0; kb < L_; kb += 128) {
        // Load K,V tiles [128,64]
        #pragma unroll
        for (int f = tid; f < 2048; f += 256) {
            int row = f >> 4, c4 = (f & 15) << 2;
            float4 v = *(const float4*)(Kg + (size_t)(kb + row)*64 + c4);
            Ks[row][c4+0] = f2tf32(v.x); Ks[row][c4+1] = f2tf32(v.y);
            Ks[row][c4+2] = f2tf32(v.z); Ks[row][c4+3] = f2tf32(v.w);
        }
        #pragma unroll
        for (int f = tid; f < 2048; f += 256) {
            int row = f >> 4, c4 = (f & 15) << 2;
            float4 v = *(const float4*)(Vg + (size_t)(kb + row)*64 + c4);
            Vs[row][c4+0] = f2tf32(v.x); Vs[row][c4+1] = f2tf32(v.y);
            Vs[row][c4+2] = f2tf32(v.z); Vs[row][c4+3] = f2tf32(v.w);
        }
        __syncthreads();

        // S = Q K^T : warp tile 64(M) x 32(N), k-dim = 64
        float sacc[4][4][4];
        #pragma unroll
        for (int i = 0; i < 4; i++)
            #pragma unroll
            for (int j = 0; j < 4; j++)
                #pragma unroll
                for (int r = 0; r < 4; r++) sacc[i][j][r] = 0.f;

        #pragma unroll
        for (int ks = 0; ks < 8; ks++) {
            const int k0 = ks * 8;
            uint32_t a[4][4], bfr[4][2];
            #pragma unroll
            for (int i = 0; i < 4; i++) {
                int r0 = wm + i*16 + g;
                a[i][0] = Qs[r0][k0 + t];     a[i][1] = Qs[r0+8][k0 + t];
                a[i][2] = Qs[r0][k0 + t + 4]; a[i][3] = Qs[r0+8][k0 + t + 4];
            }
            #pragma unroll
            for (int j = 0; j < 4; j++) {
                int c = wnS + j*8 + g;          // key index (B col) — row of Ks
                bfr[j][0] = Ks[c][k0 + t];
                bfr[j][1] = Ks[c][k0 + t + 4];
            }
            #pragma unroll
            for (int i = 0; i < 4; i++)
                #pragma unroll
                for (int j = 0; j < 4; j++)
                    mma8(sacc[i][j], a[i], bfr[j]);
        }

        // mask + exp (in regs), accumulate l partials, P -> smem (tf32)
        #pragma unroll
        for (int j = 0; j < 4; j++) {
            int c0 = wnS + j*8 + t*2;
            bool kv0 = (kb + c0)     < T;
            bool kv1 = (kb + c0 + 1) < T;
            #pragma unroll
            for (int i = 0; i < 4; i++) {
                int r0 = wm + i*16 + g;
                float p00 = __expf((qv[i*2+0] && kv0) ? sacc[i][j][0] : 0.f);
                float p01 = __expf((qv[i*2+0] && kv1) ? sacc[i][j][1] : 0.f);
                float p10 = __expf((qv[i*2+1] && kv0) ? sacc[i][j][2] : 0.f);
                float p11 = __expf((qv[i*2+1] && kv1) ? sacc[i][j][3] : 0.f);
                lp[i*2+0] += p00 + p01;
                lp[i*2+1] += p10 + p11;
                Ps[r0][c0]     = f2tf32(p00);  Ps[r0][c0+1]   = f2tf32(p01);
                Ps[r0+8][c0]   = f2tf32(p10);  Ps[r0+8][c0+1] = f2tf32(p11);
            }
        }
        __syncthreads();   // P complete (cross-warp cols) before PV

        // O += P V : warp tile 64(M) x 16(N), k-dim = 128
        #pragma unroll
        for (int ks = 0; ks < 16; ks++) {
            const int k0 = ks * 8;
            uint32_t a[4][4], bfr[2][2];
            #pragma unroll
            for (int i = 0; i < 4; i++) {
                int r0 = wm + i*16 + g;
                a[i][0] = Ps[r0][k0 + t];     a[i][1] = Ps[r0+8][k0 + t];
                a[i][2] = Ps[r0][k0 + t + 4]; a[i][3] = Ps[r0+8][k0 + t + 4];
            }
            #pragma unroll
            for (int j = 0; j < 2; j++) {
                int c = wnO + j*8 + g;          // o index (B col)
                bfr[j][0] = Vs[k0 + t][c];
                bfr[j][1] = Vs[k0 + t + 4][c];
            }
            #pragma unroll
            for (int i = 0; i < 4; i++)
                #pragma unroll
                for (int j = 0; j < 2; j++)
                    mma8(oacc[i][j], a[i], bfr[j]);
        }
        __syncthreads();   // PV reads done before next tile overwrite
    }

    // Reduce l: quad shfl (cols within warp), then across the 4 warp-cols
    #pragma unroll
    for (int i = 0; i < 8; i++) {
        lp[i] += __shfl_xor_sync(0xffffffffu, lp[i], 1);
        lp[i] += __shfl_xor_sync(0xffffffffu, lp[i], 2);
    }
    if (t == 0) {
        #pragma unroll
        for (int i = 0; i < 4; i++) {
            Lb[wm + i*16 + g][wid >> 1]     = lp[i*2+0];
            Lb[wm + i*16 + g + 8][wid >> 1] = lp[i*2+1];
        }
    }
    __syncthreads();

    // Normalize O and store concat [b,l,h*o]
    #pragma unroll
    for (int i = 0; i < 4; i++) {
        #pragma unroll
        for (int half = 0; half < 2; half++) {
            int row = wm + i*16 + g + half*8;
            float inv = 1.0f / (Lb[row][0] + Lb[row][1] + Lb[row][2] + Lb[row][3]);
            int q = qb*128 + row;
            float* dst = g_c + ((size_t)(b*L_ + q)*H_ + h) * OUT_;
            #pragma unroll
            for (int j = 0; j < 2; j++) {
                int c = wnO + j*8 + t*2;
                float2 r;
                r.x = oacc[i][j][half*2+0] * inv;
                r.y = oacc[i][j][half*2+1] * inv;
                *(float2*)(dst + c) = r;
            }
        }
    }
}

// ---------------------------------------------------------------------------
// Kernel 3: output projection  concat[32768,512] @ Wo[512,64], tf32 MMA.
// Same structure as kernel 1 (no bias, single matrix).
// ---------------------------------------------------------------------------
__global__ __launch_bounds__(256) void out_tc(
    const float* __restrict__ Wo, float* __restrict__ outp)
{
    const int mb = blockIdx.x;

    __shared__ uint32_t As[128][36];
    __shared__ uint32_t Bs[32][72];

    const int tid  = threadIdx.x;
    const int wid  = tid >> 5, lane = tid & 31;
    const int g    = lane >> 2, t = lane & 3;
    const int wm   = (wid & 3) * 32;
    const int wn   = (wid >> 2) * 32;

    float acc[2][4][4];
    #pragma unroll
    for (int i = 0; i < 2; i++)
        #pragma unroll
        for (int j = 0; j < 4; j++)
            #pragma unroll
            for (int r = 0; r < 4; r++) acc[i][j][r] = 0.f;

    const float* Abase = g_c + (size_t)mb * 128 * (H_*OUT_);

    for (int kb = 0; kb < H_*OUT_; kb += 32) {
        #pragma unroll
        for (int f = tid; f < 1024; f += 256) {
            int row = f >> 3, c4 = (f & 7) << 2;
            float4 v = *(const float4*)(Abase + row * (H_*OUT_) + kb + c4);
            As[row][c4+0] = f2tf32(v.x); As[row][c4+1] = f2tf32(v.y);
            As[row][c4+2] = f2tf32(v.z); As[row][c4+3] = f2tf32(v.w);
        }
        #pragma unroll
        for (int f = tid; f < 512; f += 256) {
            int row = f >> 4, c4 = (f & 15) << 2;
            float4 v = *(const float4*)(Wo + (kb + row) * OUT_ + c4);
            Bs[row][c4+0] = f2tf32(v.x); Bs[row][c4+1] = f2tf32(v.y);
            Bs[row][c4+2] = f2tf32(v.z); Bs[row][c4+3] = f2tf32(v.w);
        }
        __syncthreads();

        #pragma unroll
        for (int ks = 0; ks < 4; ks++) {
            const int k0 = ks * 8;
            uint32_t a[2][4], b[4][2];
            #pragma unroll
            for (int i = 0; i < 2; i++) {
                int r0 = wm + i*16 + g;
                a[i][0] = As[r0][k0 + t];     a[i][1] = As[r0+8][k0 + t];
                a[i][2] = As[r0][k0 + t + 4]; a[i][3] = As[r0+8][k0 + t + 4];
            }
            #pragma unroll
            for (int j = 0; j < 4; j++) {
                int c = wn + j*8 + g;
                b[j][0] = Bs[k0 + t][c];
                b[j][1] = Bs[k0 + t + 4][c];
            }
            #pragma unroll
            for (int i = 0; i < 2; i++)
                #pragma unroll
                for (int j = 0; j < 4; j++)
                    mma8(acc[i][j], a[i], b[j]);
        }
        __syncthreads();
    }

    #pragma unroll
    for (int i = 0; i < 2; i++) {
        #pragma unroll
        for (int half = 0; half < 2; half++) {
            int m = mb*128 + wm + i*16 + g + half*8;
            float* dst = outp + (size_t)m * OUT_;
            #pragma unroll
            for (int j = 0; j < 4; j++) {
                int c = wn + j*8 + t*2;
                float2 r;
                r.x = acc[i][j][half*2+0];
                r.y = acc[i][j][half*2+1];
                *(float2*)(dst + c) = r;
            }
        }
    }
}

// ---------------------------------------------------------------------------
extern "C" void kernel_launch(void* const* d_in, const int* in_sizes, int n_in,
                              void* d_out, int out_size)
{
    const float* joint = (const float*)d_in[0];
    // d_in[1] = delta [B,L,L,2] -- unused by the reference math (mask shape only)
    const int*   traj  = (const int*)d_in[2];
    const float* Wq    = (const float*)d_in[3];
    const float* Wk    = (const float*)d_in[4];
    const float* Wv    = (const float*)d_in[5];
    const float* bq    = (const float*)d_in[6];
    const float* bk    = (const float*)d_in[7];
    const float* bv    = (const float*)d_in[8];
    const float* Wo    = (const float*)d_in[9];
    float* out = (float*)d_out;

    static int attr_set = 0;
    if (!attr_set) {
        cudaFuncSetAttribute(attn_tc,
            cudaFuncAttributeMaxDynamicSharedMemorySize, SMEM_ATTN);
        attr_set = 1;
    }

    dim3 g1(256, 24);
    qkv_tc<<<g1, 256>>>(joint, Wq, Wk, Wv, bq, bk, bv);

    dim3 g2(8, 256);
    attn_tc<<<g2, 256, SMEM_ATTN>>>(traj);

    out_tc<<<256, 256>>>(Wo, out);
}